// round 3
// baseline (speedup 1.0000x reference)
#include <cuda_runtime.h>
#include <cuda_bf16.h>
#include <cstdint>

// ---------------- problem constants ----------------
#define NODES 100000
#define EDGES 1600000
#define HIDF  128
#define OUTF  64
#define KTOP  32

// ---------------- scratch (device globals; no allocation allowed) ----------
__device__ float g_h[(size_t)NODES * HIDF];      // dense activations
__device__ float g_t[(size_t)NODES * HIDF];      // GEMM output pre-maxk
__device__ float g_spval[(size_t)NODES * KTOP];  // compacted top-K values (scaled by deg_out^-1/2), ascending col order
__device__ ulonglong2 g_maskv[NODES];            // 128-bit column mask per row
__device__ int   g_degout[NODES];
__device__ int   g_degin[NODES];                 // raw in-degree counts
__device__ float g_souti[NODES];                 // deg_out^-1/2 (clamped)
__device__ float g_sini[NODES];                  // deg_in^-1/2 (clamped)
__device__ int   g_rowptr[NODES];                // exclusive prefix of deg_in
__device__ int   g_cursor[NODES];                // fill cursor
__device__ int   g_eidx[EDGES];                  // CSR-by-dst: src node ids
__device__ int   g_bsum[128];                    // block sums for scan
__device__ int   g_bsumx[128];                   // exclusive-scanned block sums

// ---------------- packed fp32x2 FMA (2x fp32 rate on sm_103a) --------------
__device__ __forceinline__ void fma2(float& c0, float& c1, float a, float b0, float b1) {
    asm("{\n\t"
        ".reg .b64 ra, rb, rc;\n\t"
        "mov.b64 ra, {%2,%2};\n\t"
        "mov.b64 rb, {%3,%4};\n\t"
        "mov.b64 rc, {%0,%1};\n\t"
        "fma.rn.f32x2 rc, ra, rb, rc;\n\t"
        "mov.b64 {%0,%1}, rc;\n\t"
        "}"
        : "+f"(c0), "+f"(c1)
        : "f"(a), "f"(b0), "f"(b1));
}

// ---------------- degree + CSR build kernels ----------------
__global__ void hist_kernel(const int* __restrict__ src, const int* __restrict__ dst, int E) {
    int e = blockIdx.x * blockDim.x + threadIdx.x;
    if (e < E) {
        atomicAdd(&g_degout[src[e]], 1);
        atomicAdd(&g_degin[dst[e]], 1);
    }
}

// block-wise exclusive scan of g_degin into g_rowptr (within-block), block sums out
__global__ void __launch_bounds__(1024) scan_block_kernel(int n) {
    __shared__ int sh[1024];
    int tid = threadIdx.x;
    int i = blockIdx.x * 1024 + tid;
    int v = (i < n) ? g_degin[i] : 0;
    sh[tid] = v;
    __syncthreads();
#pragma unroll
    for (int off = 1; off < 1024; off <<= 1) {
        int t = (tid >= off) ? sh[tid - off] : 0;
        __syncthreads();
        sh[tid] += t;
        __syncthreads();
    }
    if (i < n) g_rowptr[i] = sh[tid] - v;   // exclusive within block
    if (tid == 1023) g_bsum[blockIdx.x] = sh[1023];
}

__global__ void scan_top_kernel(int nb) {
    if (threadIdx.x == 0 && blockIdx.x == 0) {
        int acc = 0;
        for (int i = 0; i < nb; i++) { g_bsumx[i] = acc; acc += g_bsum[i]; }
    }
}

// finish scan + compute normalization scales
__global__ void scan_add_kernel(int n) {
    int i = blockIdx.x * blockDim.x + threadIdx.x;
    if (i < n) {
        int r = g_rowptr[i] + g_bsumx[i >> 10];
        g_rowptr[i] = r;
        g_cursor[i] = r;
        int dout = g_degout[i]; if (dout < 1) dout = 1;
        int din  = g_degin[i];  if (din  < 1) din  = 1;
        g_souti[i] = rsqrtf((float)dout);
        g_sini[i]  = rsqrtf((float)din);
    }
}

__global__ void fill_kernel(const int* __restrict__ src, const int* __restrict__ dst, int E) {
    int e = blockIdx.x * blockDim.x + threadIdx.x;
    if (e < E) {
        int d = dst[e];
        int pos = atomicAdd(&g_cursor[d], 1);
        g_eidx[pos] = src[e];
    }
}

// ---------------- fp32 GEMM: C[M,BN] = A[M,128] @ W[128,BN] + bias ----------
// BM=64 rows/block, 256 threads. W staged in two K=64 halves (smem 66KB for
// BN=128 -> 3 blocks/SM). Inner loop unrolled by 4 with float4 LDS.
template <int BN, bool RELU>
__global__ void __launch_bounds__(256, 3) gemm_kernel(
    const float* __restrict__ A, const float* __restrict__ W,
    const float* __restrict__ bias, float* __restrict__ C, int M)
{
    constexpr int BM  = 64;
    constexpr int KK  = 128;
    constexpr int AST = 132;          // As row stride (pad, float4-divisible)
    constexpr int CT  = BN / 4;       // threads along columns (4 cols each)
    constexpr int RT  = 256 / CT;     // threads along rows
    constexpr int RPT = BM / RT;      // rows per thread

    extern __shared__ float smem[];
    float* As = smem;                  // [BM][AST]
    float* Bs = smem + BM * AST;       // [64][BN] (half of W at a time)

    const int tid  = threadIdx.x;
    const int row0 = blockIdx.x * BM;

    // stage A tile (zero-fill past M) — full K=128
    constexpr int AB4 = BM * KK / 4;   // 2048 float4
    for (int i = tid; i < AB4; i += 256) {
        int r  = i >> 5;
        int c4 = i & 31;
        float4 v = make_float4(0.f, 0.f, 0.f, 0.f);
        if (row0 + r < M) v = ((const float4*)A)[(size_t)(row0 + r) * 32 + c4];
        *(float4*)&As[r * AST + c4 * 4] = v;
    }

    const int tx = tid % CT;
    const int ty = tid / CT;

    float acc[RPT][4];
#pragma unroll
    for (int r = 0; r < RPT; r++) {
        acc[r][0] = 0.f; acc[r][1] = 0.f; acc[r][2] = 0.f; acc[r][3] = 0.f;
    }

    constexpr int WB4 = 64 * BN / 4;   // float4s per W half

#pragma unroll
    for (int ks = 0; ks < 2; ks++) {
        // stage this K-half of W
        for (int i = tid; i < WB4; i += 256)
            ((float4*)Bs)[i] = ((const float4*)W)[ks * WB4 + i];
        __syncthreads();

#pragma unroll 4
        for (int k4 = 0; k4 < 16; k4++) {
            float4 b0 = *(const float4*)&Bs[(k4 * 4 + 0) * BN + tx * 4];
            float4 b1 = *(const float4*)&Bs[(k4 * 4 + 1) * BN + tx * 4];
            float4 b2 = *(const float4*)&Bs[(k4 * 4 + 2) * BN + tx * 4];
            float4 b3 = *(const float4*)&Bs[(k4 * 4 + 3) * BN + tx * 4];
#pragma unroll
            for (int r = 0; r < RPT; r++) {
                float4 a = *(const float4*)&As[(ty * RPT + r) * AST + ks * 64 + k4 * 4];
                fma2(acc[r][0], acc[r][1], a.x, b0.x, b0.y);
                fma2(acc[r][2], acc[r][3], a.x, b0.z, b0.w);
                fma2(acc[r][0], acc[r][1], a.y, b1.x, b1.y);
                fma2(acc[r][2], acc[r][3], a.y, b1.z, b1.w);
                fma2(acc[r][0], acc[r][1], a.z, b2.x, b2.y);
                fma2(acc[r][2], acc[r][3], a.z, b2.z, b2.w);
                fma2(acc[r][0], acc[r][1], a.w, b3.x, b3.y);
                fma2(acc[r][2], acc[r][3], a.w, b3.z, b3.w);
            }
        }
        __syncthreads();
    }

    float4 bi = *(const float4*)&bias[tx * 4];
#pragma unroll
    for (int r = 0; r < RPT; r++) {
        int row = row0 + ty * RPT + r;
        if (row < M) {
            float4 o;
            o.x = acc[r][0] + bi.x;
            o.y = acc[r][1] + bi.y;
            o.z = acc[r][2] + bi.z;
            o.w = acc[r][3] + bi.w;
            if (RELU) {
                o.x = fmaxf(o.x, 0.f); o.y = fmaxf(o.y, 0.f);
                o.z = fmaxf(o.z, 0.f); o.w = fmaxf(o.w, 0.f);
            }
            *(float4*)&C[(size_t)row * BN + tx * 4] = o;
        }
    }
}

// ---------------- MaxK: exact top-32 of 128 -> (mask, compacted scaled vals) -
// One warp per row; bitwise radix-select; ties by ascending index (matches
// lax.top_k). Values written in ascending column order, scaled by souti.
__global__ void maxk_kernel(int M) {
    int warp = (blockIdx.x * blockDim.x + threadIdx.x) >> 5;
    int lane = threadIdx.x & 31;
    if (warp >= M) return;

    const float* rowp = g_t + (size_t)warp * HIDF;
    float v[4];
    unsigned key[4];
#pragma unroll
    for (int j = 0; j < 4; j++) {
        v[j] = rowp[lane + 32 * j];            // column = 32*j + lane
        unsigned u = __float_as_uint(v[j]);
        key[j] = (u & 0x80000000u) ? ~u : (u | 0x80000000u);
    }

    unsigned thr = 0u;
#pragma unroll
    for (int b = 31; b >= 0; b--) {
        unsigned cand = thr | (1u << b);
        int cnt = 0;
#pragma unroll
        for (int j = 0; j < 4; j++)
            cnt += __popc(__ballot_sync(0xffffffffu, key[j] >= cand));
        if (cnt >= KTOP) thr = cand;
    }

    int rem;
    {
        int cnt_gt = 0;
#pragma unroll
        for (int j = 0; j < 4; j++)
            cnt_gt += __popc(__ballot_sync(0xffffffffu, key[j] > thr));
        rem = KTOP - cnt_gt;
    }

    const float s = g_souti[warp];
    const unsigned lmlt = (1u << lane) - 1u;
    float* ov = g_spval + (size_t)warp * KTOP;

    unsigned bs[4];
    int off = 0;
#pragma unroll
    for (int j = 0; j < 4; j++) {
        unsigned beq = __ballot_sync(0xffffffffu, key[j] == thr);
        int neq  = __popc(beq);
        int take = rem < neq ? rem : neq;
        if (take < 0) take = 0;
        rem -= take;
        bool sel = (key[j] > thr) || ((key[j] == thr) && (__popc(beq & lmlt) < take));
        unsigned bsel = __ballot_sync(0xffffffffu, sel);
        bs[j] = bsel;
        if (sel) {
            int pos = off + __popc(bsel & lmlt);   // ascending column order
            ov[pos] = v[j] * s;
        }
        off += __popc(bsel);
    }

    if (lane == 0) {
        ulonglong2 m;
        m.x = (unsigned long long)bs[0] | ((unsigned long long)bs[1] << 32);
        m.y = (unsigned long long)bs[2] | ((unsigned long long)bs[3] << 32);
        g_maskv[warp] = m;
    }
}

// ---------------- compact-sparse edge accumulate ----------------------------
// lane owns columns [4*lane, 4*lane+4); reconstruct positions from 128-bit mask.
__device__ __forceinline__ void edge_acc(int s, unsigned long long m0, unsigned long long m1,
                                         int lane, float acc[4]) {
    const float* vp = g_spval + (size_t)s * KTOP;
    unsigned bits;
    int rank;
    if (lane < 16) {
        int sh = lane * 4;
        rank = __popcll(m0 & ((1ull << sh) - 1ull));
        bits = (unsigned)(m0 >> sh) & 0xFu;
    } else {
        int sh = lane * 4 - 64;
        rank = __popcll(m0) + __popcll(m1 & ((1ull << sh) - 1ull));
        bits = (unsigned)(m1 >> sh) & 0xFu;
    }
    if (bits & 1u) { acc[0] += vp[rank]; rank++; }
    if (bits & 2u) { acc[1] += vp[rank]; rank++; }
    if (bits & 4u) { acc[2] += vp[rank]; rank++; }
    if (bits & 8u) { acc[3] += vp[rank]; }
}

// ---------------- CSR gather: h[d,:] = sini[d]*sum_{e in in(d)} sp[src_e] + bg
// One warp per dst node; register accumulators; 4-deep edge unroll for MLP.
__global__ void __launch_bounds__(256) gather_kernel(const float* __restrict__ bg, int M) {
    int w    = (blockIdx.x * blockDim.x + threadIdx.x) >> 5;
    int lane = threadIdx.x & 31;
    if (w >= M) return;

    float acc[4] = {0.f, 0.f, 0.f, 0.f};

    const int beg = g_rowptr[w];
    const int end = beg + g_degin[w];

    int e = beg;
    for (; e + 4 <= end; e += 4) {
        int s0 = g_eidx[e];
        int s1 = g_eidx[e + 1];
        int s2 = g_eidx[e + 2];
        int s3 = g_eidx[e + 3];
        ulonglong2 k0 = g_maskv[s0];
        ulonglong2 k1 = g_maskv[s1];
        ulonglong2 k2 = g_maskv[s2];
        ulonglong2 k3 = g_maskv[s3];
        edge_acc(s0, k0.x, k0.y, lane, acc);
        edge_acc(s1, k1.x, k1.y, lane, acc);
        edge_acc(s2, k2.x, k2.y, lane, acc);
        edge_acc(s3, k3.x, k3.y, lane, acc);
    }
    for (; e < end; e++) {
        int s0 = g_eidx[e];
        ulonglong2 k0 = g_maskv[s0];
        edge_acc(s0, k0.x, k0.y, lane, acc);
    }

    const float sc = g_sini[w];
    float4 b = ((const float4*)bg)[lane];
    float4 o;
    o.x = acc[0] * sc + b.x;
    o.y = acc[1] * sc + b.y;
    o.z = acc[2] * sc + b.z;
    o.w = acc[3] * sc + b.w;
    ((float4*)(g_h + (size_t)w * HIDF))[lane] = o;
}

// ---------------- launch -----------------------------------------------------
extern "C" void kernel_launch(void* const* d_in, const int* in_sizes, int n_in,
                              void* d_out, int out_size) {
    const float* x    = (const float*)d_in[0];
    const int*   src  = (const int*)d_in[1];
    const int*   dst  = (const int*)d_in[2];
    const float* W_in = (const float*)d_in[3];
    const float* b_in = (const float*)d_in[4];
    const float* W1   = (const float*)d_in[5];
    const float* b1   = (const float*)d_in[6];
    const float* bg1  = (const float*)d_in[7];
    const float* W2   = (const float*)d_in[8];
    const float* b2   = (const float*)d_in[9];
    const float* bg2  = (const float*)d_in[10];
    const float* Wo   = (const float*)d_in[11];
    const float* bo   = (const float*)d_in[12];
    float* out = (float*)d_out;

    const int M = in_sizes[0] / HIDF;   // 100000
    const int E = in_sizes[1];          // 1600000

    const int SMEM128 = (64 * 132 + 64 * 128) * 4;  // 66560
    const int SMEM64  = (64 * 132 + 64 * 64) * 4;   // 50176
    cudaFuncSetAttribute(gemm_kernel<128, true>,  cudaFuncAttributeMaxDynamicSharedMemorySize, SMEM128);
    cudaFuncSetAttribute(gemm_kernel<128, false>, cudaFuncAttributeMaxDynamicSharedMemorySize, SMEM128);
    cudaFuncSetAttribute(gemm_kernel<64,  false>, cudaFuncAttributeMaxDynamicSharedMemorySize, SMEM64);

    void *ph, *pt, *pdo, *pdi;
    cudaGetSymbolAddress(&ph,  g_h);
    cudaGetSymbolAddress(&pt,  g_t);
    cudaGetSymbolAddress(&pdo, g_degout);
    cudaGetSymbolAddress(&pdi, g_degin);
    float* h = (float*)ph;
    float* t = (float*)pt;

    const int TB = 256;
    const int gemm_grid = (M + 63) / 64;
    const int warp_grid = (M * 32 + TB - 1) / TB;      // 1 warp per node
    const int node_grid = (M + TB - 1) / TB;
    const int edge_grid = (E + TB - 1) / TB;
    const int NB        = (M + 1023) / 1024;           // scan blocks

    // ---- degrees + CSR build ----
    cudaMemsetAsync(pdo, 0, (size_t)M * sizeof(int));
    cudaMemsetAsync(pdi, 0, (size_t)M * sizeof(int));
    hist_kernel<<<edge_grid, TB>>>(src, dst, E);
    scan_block_kernel<<<NB, 1024>>>(M);
    scan_top_kernel<<<1, 32>>>(NB);
    scan_add_kernel<<<node_grid, TB>>>(M);
    fill_kernel<<<edge_grid, TB>>>(src, dst, E);

    // ---- input projection + relu ----
    gemm_kernel<128, true><<<gemm_grid, TB, SMEM128>>>(x, W_in, b_in, h, M);

    // ---- layer 1 ----
    gemm_kernel<128, false><<<gemm_grid, TB, SMEM128>>>(h, W1, b1, t, M);
    maxk_kernel<<<warp_grid, TB>>>(M);
    gather_kernel<<<warp_grid, TB>>>(bg1, M);

    // ---- layer 2 ----
    gemm_kernel<128, false><<<gemm_grid, TB, SMEM128>>>(h, W2, b2, t, M);
    maxk_kernel<<<warp_grid, TB>>>(M);
    gather_kernel<<<warp_grid, TB>>>(bg2, M);

    // ---- output projection ----
    gemm_kernel<64, false><<<gemm_grid, TB, SMEM64>>>(h, Wo, bo, out, M);
}

// round 4
// speedup vs baseline: 1.1785x; 1.1785x over previous
#include <cuda_runtime.h>
#include <cuda_bf16.h>
#include <cstdint>

// ---------------- problem constants ----------------
#define NODES 100000
#define EDGES 1600000
#define HIDF  128
#define OUTF  64
#define KTOP  32

// ---------------- scratch (device globals; no allocation allowed) ----------
__device__ float g_h[(size_t)NODES * HIDF];      // dense activations
__device__ float g_t[(size_t)NODES * HIDF];      // GEMM output; maxk rewrites in place
__device__ int   g_degout[NODES];
__device__ int   g_degin[NODES];                 // raw in-degree counts
__device__ float g_souti[NODES];                 // deg_out^-1/2 (clamped)
__device__ float g_sini[NODES];                  // deg_in^-1/2 (clamped)
__device__ int   g_rowptr[NODES];                // exclusive prefix of deg_in
__device__ int   g_cursor[NODES];                // fill cursor
__device__ int   g_eidx[EDGES];                  // CSR-by-dst: src node ids
__device__ int   g_bsum[128];                    // block sums for scan
__device__ int   g_bsumx[128];                   // exclusive-scanned block sums

// ---------------- packed fp32x2 FMA (2x fp32 rate on sm_103a) --------------
__device__ __forceinline__ void fma2(float& c0, float& c1, float a, float b0, float b1) {
    asm("{\n\t"
        ".reg .b64 ra, rb, rc;\n\t"
        "mov.b64 ra, {%2,%2};\n\t"
        "mov.b64 rb, {%3,%4};\n\t"
        "mov.b64 rc, {%0,%1};\n\t"
        "fma.rn.f32x2 rc, ra, rb, rc;\n\t"
        "mov.b64 {%0,%1}, rc;\n\t"
        "}"
        : "+f"(c0), "+f"(c1)
        : "f"(a), "f"(b0), "f"(b1));
}

// ---------------- degree + CSR build kernels ----------------
__global__ void hist_kernel(const int* __restrict__ src, const int* __restrict__ dst, int E) {
    int e = blockIdx.x * blockDim.x + threadIdx.x;
    if (e < E) {
        atomicAdd(&g_degout[src[e]], 1);
        atomicAdd(&g_degin[dst[e]], 1);
    }
}

__global__ void __launch_bounds__(1024) scan_block_kernel(int n) {
    __shared__ int sh[1024];
    int tid = threadIdx.x;
    int i = blockIdx.x * 1024 + tid;
    int v = (i < n) ? g_degin[i] : 0;
    sh[tid] = v;
    __syncthreads();
#pragma unroll
    for (int off = 1; off < 1024; off <<= 1) {
        int t = (tid >= off) ? sh[tid - off] : 0;
        __syncthreads();
        sh[tid] += t;
        __syncthreads();
    }
    if (i < n) g_rowptr[i] = sh[tid] - v;   // exclusive within block
    if (tid == 1023) g_bsum[blockIdx.x] = sh[1023];
}

__global__ void scan_top_kernel(int nb) {
    if (threadIdx.x == 0 && blockIdx.x == 0) {
        int acc = 0;
        for (int i = 0; i < nb; i++) { g_bsumx[i] = acc; acc += g_bsum[i]; }
    }
}

__global__ void scan_add_kernel(int n) {
    int i = blockIdx.x * blockDim.x + threadIdx.x;
    if (i < n) {
        int r = g_rowptr[i] + g_bsumx[i >> 10];
        g_rowptr[i] = r;
        g_cursor[i] = r;
        int dout = g_degout[i]; if (dout < 1) dout = 1;
        int din  = g_degin[i];  if (din  < 1) din  = 1;
        g_souti[i] = rsqrtf((float)dout);
        g_sini[i]  = rsqrtf((float)din);
    }
}

__global__ void fill_kernel(const int* __restrict__ src, const int* __restrict__ dst, int E) {
    int e = blockIdx.x * blockDim.x + threadIdx.x;
    if (e < E) {
        int d = dst[e];
        int pos = atomicAdd(&g_cursor[d], 1);
        g_eidx[pos] = src[e];
    }
}

// ---------------- fp32 GEMM: C[M,BN] = A[M,128] @ W[128,BN] + bias ----------
template <int BN, bool RELU>
__global__ void __launch_bounds__(256, 3) gemm_kernel(
    const float* __restrict__ A, const float* __restrict__ W,
    const float* __restrict__ bias, float* __restrict__ C, int M)
{
    constexpr int BM  = 64;
    constexpr int KK  = 128;
    constexpr int AST = 132;
    constexpr int CT  = BN / 4;
    constexpr int RT  = 256 / CT;
    constexpr int RPT = BM / RT;

    extern __shared__ float smem[];
    float* As = smem;
    float* Bs = smem + BM * AST;

    const int tid  = threadIdx.x;
    const int row0 = blockIdx.x * BM;

    constexpr int AB4 = BM * KK / 4;
    for (int i = tid; i < AB4; i += 256) {
        int r  = i >> 5;
        int c4 = i & 31;
        float4 v = make_float4(0.f, 0.f, 0.f, 0.f);
        if (row0 + r < M) v = ((const float4*)A)[(size_t)(row0 + r) * 32 + c4];
        *(float4*)&As[r * AST + c4 * 4] = v;
    }

    const int tx = tid % CT;
    const int ty = tid / CT;

    float acc[RPT][4];
#pragma unroll
    for (int r = 0; r < RPT; r++) {
        acc[r][0] = 0.f; acc[r][1] = 0.f; acc[r][2] = 0.f; acc[r][3] = 0.f;
    }

    constexpr int WB4 = 64 * BN / 4;

#pragma unroll
    for (int ks = 0; ks < 2; ks++) {
        for (int i = tid; i < WB4; i += 256)
            ((float4*)Bs)[i] = ((const float4*)W)[ks * WB4 + i];
        __syncthreads();

#pragma unroll 4
        for (int k4 = 0; k4 < 16; k4++) {
            float4 b0 = *(const float4*)&Bs[(k4 * 4 + 0) * BN + tx * 4];
            float4 b1 = *(const float4*)&Bs[(k4 * 4 + 1) * BN + tx * 4];
            float4 b2 = *(const float4*)&Bs[(k4 * 4 + 2) * BN + tx * 4];
            float4 b3 = *(const float4*)&Bs[(k4 * 4 + 3) * BN + tx * 4];
#pragma unroll
            for (int r = 0; r < RPT; r++) {
                float4 a = *(const float4*)&As[(ty * RPT + r) * AST + ks * 64 + k4 * 4];
                fma2(acc[r][0], acc[r][1], a.x, b0.x, b0.y);
                fma2(acc[r][2], acc[r][3], a.x, b0.z, b0.w);
                fma2(acc[r][0], acc[r][1], a.y, b1.x, b1.y);
                fma2(acc[r][2], acc[r][3], a.y, b1.z, b1.w);
                fma2(acc[r][0], acc[r][1], a.z, b2.x, b2.y);
                fma2(acc[r][2], acc[r][3], a.z, b2.z, b2.w);
                fma2(acc[r][0], acc[r][1], a.w, b3.x, b3.y);
                fma2(acc[r][2], acc[r][3], a.w, b3.z, b3.w);
            }
        }
        __syncthreads();
    }

    float4 bi = *(const float4*)&bias[tx * 4];
#pragma unroll
    for (int r = 0; r < RPT; r++) {
        int row = row0 + ty * RPT + r;
        if (row < M) {
            float4 o;
            o.x = acc[r][0] + bi.x;
            o.y = acc[r][1] + bi.y;
            o.z = acc[r][2] + bi.z;
            o.w = acc[r][3] + bi.w;
            if (RELU) {
                o.x = fmaxf(o.x, 0.f); o.y = fmaxf(o.y, 0.f);
                o.z = fmaxf(o.z, 0.f); o.w = fmaxf(o.w, 0.f);
            }
            *(float4*)&C[(size_t)row * BN + tx * 4] = o;
        }
    }
}

// ---------------- MaxK: exact top-32 of 128, rewrite row in place -----------
// t[row] <- (selected ? v : 0) * deg_out^-1/2. One warp per row; bitwise
// radix-select on float-ordered keys; ties by ascending index (lax.top_k).
__global__ void maxk_kernel(int M) {
    int warp = (blockIdx.x * blockDim.x + threadIdx.x) >> 5;
    int lane = threadIdx.x & 31;
    if (warp >= M) return;

    float* rowp = g_t + (size_t)warp * HIDF;
    float v[4];
    unsigned key[4];
#pragma unroll
    for (int j = 0; j < 4; j++) {
        v[j] = rowp[lane + 32 * j];
        unsigned u = __float_as_uint(v[j]);
        key[j] = (u & 0x80000000u) ? ~u : (u | 0x80000000u);
    }

    unsigned thr = 0u;
#pragma unroll
    for (int b = 31; b >= 0; b--) {
        unsigned cand = thr | (1u << b);
        int cnt = 0;
#pragma unroll
        for (int j = 0; j < 4; j++)
            cnt += __popc(__ballot_sync(0xffffffffu, key[j] >= cand));
        if (cnt >= KTOP) thr = cand;
    }

    int rem;
    {
        int cnt_gt = 0;
#pragma unroll
        for (int j = 0; j < 4; j++)
            cnt_gt += __popc(__ballot_sync(0xffffffffu, key[j] > thr));
        rem = KTOP - cnt_gt;
    }

    const float s = g_souti[warp];
    const unsigned lmlt = (1u << lane) - 1u;

#pragma unroll
    for (int j = 0; j < 4; j++) {
        unsigned beq = __ballot_sync(0xffffffffu, key[j] == thr);
        int neq  = __popc(beq);
        int take = rem < neq ? rem : neq;
        if (take < 0) take = 0;
        rem -= take;
        bool sel = (key[j] > thr) || ((key[j] == thr) && (__popc(beq & lmlt) < take));
        rowp[lane + 32 * j] = sel ? (v[j] * s) : 0.f;
    }
}

// ---------------- CSR gather: h[d,:] = sini[d]*sum_{e in in(d)} t[src_e,:] + bg
// One warp per dst; lane owns 4 columns; one float4 LDG per lane per edge.
__global__ void __launch_bounds__(256) gather_kernel(const float* __restrict__ bg, int M) {
    int w    = (blockIdx.x * blockDim.x + threadIdx.x) >> 5;
    int lane = threadIdx.x & 31;
    if (w >= M) return;

    float acc0 = 0.f, acc1 = 0.f, acc2 = 0.f, acc3 = 0.f;

    const int beg = g_rowptr[w];
    const int end = beg + g_degin[w];
    const float4* tp = (const float4*)g_t;

    int e = beg;
    for (; e + 4 <= end; e += 4) {
        int s0 = __ldg(&g_eidx[e]);
        int s1 = __ldg(&g_eidx[e + 1]);
        int s2 = __ldg(&g_eidx[e + 2]);
        int s3 = __ldg(&g_eidx[e + 3]);
        float4 v0 = __ldg(&tp[(size_t)s0 * 32 + lane]);
        float4 v1 = __ldg(&tp[(size_t)s1 * 32 + lane]);
        float4 v2 = __ldg(&tp[(size_t)s2 * 32 + lane]);
        float4 v3 = __ldg(&tp[(size_t)s3 * 32 + lane]);
        acc0 += v0.x; acc1 += v0.y; acc2 += v0.z; acc3 += v0.w;
        acc0 += v1.x; acc1 += v1.y; acc2 += v1.z; acc3 += v1.w;
        acc0 += v2.x; acc1 += v2.y; acc2 += v2.z; acc3 += v2.w;
        acc0 += v3.x; acc1 += v3.y; acc2 += v3.z; acc3 += v3.w;
    }
    for (; e < end; e++) {
        int s0 = __ldg(&g_eidx[e]);
        float4 v0 = __ldg(&tp[(size_t)s0 * 32 + lane]);
        acc0 += v0.x; acc1 += v0.y; acc2 += v0.z; acc3 += v0.w;
    }

    const float sc = g_sini[w];
    float4 b = __ldg(&((const float4*)bg)[lane]);
    float4 o;
    o.x = acc0 * sc + b.x;
    o.y = acc1 * sc + b.y;
    o.z = acc2 * sc + b.z;
    o.w = acc3 * sc + b.w;
    ((float4*)(g_h + (size_t)w * HIDF))[lane] = o;
}

// ---------------- launch -----------------------------------------------------
extern "C" void kernel_launch(void* const* d_in, const int* in_sizes, int n_in,
                              void* d_out, int out_size) {
    const float* x    = (const float*)d_in[0];
    const int*   src  = (const int*)d_in[1];
    const int*   dst  = (const int*)d_in[2];
    const float* W_in = (const float*)d_in[3];
    const float* b_in = (const float*)d_in[4];
    const float* W1   = (const float*)d_in[5];
    const float* b1   = (const float*)d_in[6];
    const float* bg1  = (const float*)d_in[7];
    const float* W2   = (const float*)d_in[8];
    const float* b2   = (const float*)d_in[9];
    const float* bg2  = (const float*)d_in[10];
    const float* Wo   = (const float*)d_in[11];
    const float* bo   = (const float*)d_in[12];
    float* out = (float*)d_out;

    const int M = in_sizes[0] / HIDF;   // 100000
    const int E = in_sizes[1];          // 1600000

    const int SMEM128 = (64 * 132 + 64 * 128) * 4;  // 66560
    const int SMEM64  = (64 * 132 + 64 * 64) * 4;   // 50176
    cudaFuncSetAttribute(gemm_kernel<128, true>,  cudaFuncAttributeMaxDynamicSharedMemorySize, SMEM128);
    cudaFuncSetAttribute(gemm_kernel<128, false>, cudaFuncAttributeMaxDynamicSharedMemorySize, SMEM128);
    cudaFuncSetAttribute(gemm_kernel<64,  false>, cudaFuncAttributeMaxDynamicSharedMemorySize, SMEM64);

    void *ph, *pt, *pdo, *pdi;
    cudaGetSymbolAddress(&ph,  g_h);
    cudaGetSymbolAddress(&pt,  g_t);
    cudaGetSymbolAddress(&pdo, g_degout);
    cudaGetSymbolAddress(&pdi, g_degin);
    float* h = (float*)ph;
    float* t = (float*)pt;

    const int TB = 256;
    const int gemm_grid = (M + 63) / 64;
    const int warp_grid = (M * 32 + TB - 1) / TB;      // 1 warp per node
    const int node_grid = (M + TB - 1) / TB;
    const int edge_grid = (E + TB - 1) / TB;
    const int NB        = (M + 1023) / 1024;

    // ---- degrees + CSR build ----
    cudaMemsetAsync(pdo, 0, (size_t)M * sizeof(int));
    cudaMemsetAsync(pdi, 0, (size_t)M * sizeof(int));
    hist_kernel<<<edge_grid, TB>>>(src, dst, E);
    scan_block_kernel<<<NB, 1024>>>(M);
    scan_top_kernel<<<1, 32>>>(NB);
    scan_add_kernel<<<node_grid, TB>>>(M);
    fill_kernel<<<edge_grid, TB>>>(src, dst, E);

    // ---- input projection + relu ----
    gemm_kernel<128, true><<<gemm_grid, TB, SMEM128>>>(x, W_in, b_in, h, M);

    // ---- layer 1 ----
    gemm_kernel<128, false><<<gemm_grid, TB, SMEM128>>>(h, W1, b1, t, M);
    maxk_kernel<<<warp_grid, TB>>>(M);
    gather_kernel<<<warp_grid, TB>>>(bg1, M);

    // ---- layer 2 ----
    gemm_kernel<128, false><<<gemm_grid, TB, SMEM128>>>(h, W2, b2, t, M);
    maxk_kernel<<<warp_grid, TB>>>(M);
    gather_kernel<<<warp_grid, TB>>>(bg2, M);

    // ---- output projection ----
    gemm_kernel<64, false><<<gemm_grid, TB, SMEM64>>>(h, Wo, bo, out, M);
}

// round 6
// speedup vs baseline: 1.2664x; 1.0746x over previous
#include <cuda_runtime.h>
#include <cuda_bf16.h>
#include <cstdint>

// ---------------- problem constants ----------------
#define NODES 100000
#define EDGES 1600000
#define HIDF  128
#define OUTF  64
#define KTOP  32

// ---------------- scratch (device globals; no allocation allowed) ----------
__device__ float g_h[(size_t)NODES * HIDF];      // dense activations
__device__ float g_t[(size_t)NODES * HIDF];      // GEMM output; maxk rewrites in place
__device__ int   g_degout[NODES];
__device__ int   g_degin[NODES];
__device__ float g_souti[NODES];                 // deg_out^-1/2 (clamped)
__device__ float g_sini[NODES];                  // deg_in^-1/2 (clamped)
__device__ int   g_rowptr[NODES];
__device__ int   g_cursor[NODES];
__device__ int   g_eidx[EDGES];                  // CSR-by-dst: src node ids
__device__ int   g_bsum[128];
__device__ int   g_bsumx[128];
// pre-split transposed weights, bf16, plain [n][k] row-major (k contiguous)
__device__ __nv_bfloat16 g_wbh[3 * 128 * 128];   // hi of W_in^T, W1^T, W2^T
__device__ __nv_bfloat16 g_wbl[3 * 128 * 128];   // lo
__device__ __nv_bfloat16 g_obh[64 * 128];        // W_out^T hi
__device__ __nv_bfloat16 g_obl[64 * 128];        // W_out^T lo

__device__ __forceinline__ uint32_t smem_to_u32(const void* smem_ptr) {
    uint32_t addr;
    asm("{ .reg .u64 tmp; cvta.to.shared.u64 tmp, %1; cvt.u32.u64 %0, tmp; }"
        : "=r"(addr) : "l"(smem_ptr));
    return addr;
}

__device__ __forceinline__ void ldsm_x4(uint32_t r[4], uint32_t addr) {
    asm volatile("ldmatrix.sync.aligned.m8n8.x4.shared.b16 {%0,%1,%2,%3}, [%4];"
        : "=r"(r[0]), "=r"(r[1]), "=r"(r[2]), "=r"(r[3]) : "r"(addr));
}

__device__ __forceinline__ void mma_bf16(float c[4], const uint32_t a[4],
                                         uint32_t b0, uint32_t b1) {
    asm volatile(
        "mma.sync.aligned.m16n8k16.row.col.f32.bf16.bf16.f32 "
        "{%0,%1,%2,%3}, {%4,%5,%6,%7}, {%8,%9}, {%0,%1,%2,%3};"
        : "+f"(c[0]), "+f"(c[1]), "+f"(c[2]), "+f"(c[3])
        : "r"(a[0]), "r"(a[1]), "r"(a[2]), "r"(a[3]), "r"(b0), "r"(b1));
}

// ---------------- degree + CSR build kernels ----------------
__global__ void hist_kernel(const int* __restrict__ src, const int* __restrict__ dst, int E) {
    int e = blockIdx.x * blockDim.x + threadIdx.x;
    if (e < E) {
        atomicAdd(&g_degout[src[e]], 1);
        atomicAdd(&g_degin[dst[e]], 1);
    }
}

__global__ void __launch_bounds__(1024) scan_block_kernel(int n) {
    __shared__ int sh[1024];
    int tid = threadIdx.x;
    int i = blockIdx.x * 1024 + tid;
    int v = (i < n) ? g_degin[i] : 0;
    sh[tid] = v;
    __syncthreads();
#pragma unroll
    for (int off = 1; off < 1024; off <<= 1) {
        int t = (tid >= off) ? sh[tid - off] : 0;
        __syncthreads();
        sh[tid] += t;
        __syncthreads();
    }
    if (i < n) g_rowptr[i] = sh[tid] - v;
    if (tid == 1023) g_bsum[blockIdx.x] = sh[1023];
}

__global__ void scan_top_kernel(int nb) {
    if (threadIdx.x == 0 && blockIdx.x == 0) {
        int acc = 0;
        for (int i = 0; i < nb; i++) { g_bsumx[i] = acc; acc += g_bsum[i]; }
    }
}

__global__ void scan_add_kernel(int n) {
    int i = blockIdx.x * blockDim.x + threadIdx.x;
    if (i < n) {
        int r = g_rowptr[i] + g_bsumx[i >> 10];
        g_rowptr[i] = r;
        g_cursor[i] = r;
        int dout = g_degout[i]; if (dout < 1) dout = 1;
        int din  = g_degin[i];  if (din  < 1) din  = 1;
        g_souti[i] = rsqrtf((float)dout);
        g_sini[i]  = rsqrtf((float)din);
    }
}

__global__ void fill_kernel(const int* __restrict__ src, const int* __restrict__ dst, int E) {
    int e = blockIdx.x * blockDim.x + threadIdx.x;
    if (e < E) {
        int d = dst[e];
        int pos = atomicAdd(&g_cursor[d], 1);
        g_eidx[pos] = src[e];
    }
}

// ---------------- weight prep: transpose + bf16 hi/lo split -----------------
// bh[n*128 + k] = hi(W[k][n]);  bl = lo.  (W is [128, N] row-major.)
__global__ void wsplit_kernel(const float* __restrict__ W,
                              __nv_bfloat16* __restrict__ bh,
                              __nv_bfloat16* __restrict__ bl, int N) {
    int i = blockIdx.x * blockDim.x + threadIdx.x;   // over N*128
    if (i >= N * 128) return;
    int n = i >> 7;
    int k = i & 127;
    float v = W[k * N + n];
    __nv_bfloat16 h = __float2bfloat16(v);
    __nv_bfloat16 l = __float2bfloat16(v - __bfloat162float(h));
    bh[n * 128 + k] = h;
    bl[n * 128 + k] = l;
}

// ---------------- HMMA bf16x3 GEMM: C[M,BN] = A[M,128]@W + bias -------------
// mma.sync m16n8k16. A split hi/lo bf16 in smem (stride 136 bf16, conflict-free
// ldmatrix); W^T hi/lo staged from pre-split global. 3 products per tile.
template <int BN, bool RELU>
__global__ void __launch_bounds__(256, 2) hmma_gemm_kernel(
    const float* __restrict__ A,
    const __nv_bfloat16* __restrict__ wbh,
    const __nv_bfloat16* __restrict__ wbl,
    const float* __restrict__ bias,
    float* __restrict__ C, int M)
{
    constexpr int NW = BN / 32;          // n-warps
    constexpr int MW = 8 / NW;           // m-warps
    constexpr int BM = MW * 32;          // rows per block
    constexpr int LDB = 272;             // 136 bf16 row stride, bytes
    constexpr int OFF_AH = 0;
    constexpr int OFF_AL = OFF_AH + BM * LDB;
    constexpr int OFF_WH = OFF_AL + BM * LDB;
    constexpr int OFF_WL = OFF_WH + BN * LDB;
    constexpr int OFF_BI = OFF_WL + BN * LDB;

    extern __shared__ char smem[];
    const uint32_t sb = smem_to_u32(smem);
    const int tid  = threadIdx.x;
    const int wid  = tid >> 5;
    const int lane = tid & 31;
    const int row0 = blockIdx.x * BM;
    const int warp_m = wid / NW;
    const int warp_n = wid % NW;

    // ---- stage W^T hi/lo (u32 granules: 64 per 128-bf16 row) ----
    for (int i = tid; i < BN * 64; i += 256) {
        int n = i >> 6, kp = i & 63;
        ((uint32_t*)(smem + OFF_WH + n * LDB))[kp] = ((const uint32_t*)wbh)[i];
        ((uint32_t*)(smem + OFF_WL + n * LDB))[kp] = ((const uint32_t*)wbl)[i];
    }
    if (tid < BN) ((float*)(smem + OFF_BI))[tid] = bias[tid];

    // ---- stage A tile, f32 -> (hi, lo) bf16 ----
    for (int i = tid; i < BM * 32; i += 256) {
        int r = i >> 5, c4 = i & 31;
        float4 v = make_float4(0.f, 0.f, 0.f, 0.f);
        if (row0 + r < M) v = ((const float4*)A)[(size_t)(row0 + r) * 32 + c4];
        __nv_bfloat16 h0 = __float2bfloat16(v.x);
        __nv_bfloat16 h1 = __float2bfloat16(v.y);
        __nv_bfloat16 h2 = __float2bfloat16(v.z);
        __nv_bfloat16 h3 = __float2bfloat16(v.w);
        __nv_bfloat16 l0 = __float2bfloat16(v.x - __bfloat162float(h0));
        __nv_bfloat16 l1 = __float2bfloat16(v.y - __bfloat162float(h1));
        __nv_bfloat16 l2 = __float2bfloat16(v.z - __bfloat162float(h2));
        __nv_bfloat16 l3 = __float2bfloat16(v.w - __bfloat162float(h3));
        __nv_bfloat162 hp0; hp0.x = h0; hp0.y = h1;
        __nv_bfloat162 hp1; hp1.x = h2; hp1.y = h3;
        __nv_bfloat162 lp0; lp0.x = l0; lp0.y = l1;
        __nv_bfloat162 lp1; lp1.x = l2; lp1.y = l3;
        uint32_t* dh = (uint32_t*)(smem + OFF_AH + r * LDB);
        uint32_t* dl = (uint32_t*)(smem + OFF_AL + r * LDB);
        dh[c4 * 2]     = *(uint32_t*)&hp0;
        dh[c4 * 2 + 1] = *(uint32_t*)&hp1;
        dl[c4 * 2]     = *(uint32_t*)&lp0;
        dl[c4 * 2 + 1] = *(uint32_t*)&lp1;
    }
    __syncthreads();

    // lane-derived ldmatrix offsets
    // A x4: matrices (m0-7,k0-7),(m8-15,k0-7),(m0-7,k8-15),(m8-15,k8-15)
    const int a_row  = warp_m * 32 + (lane & 15);
    const int a_koff = (lane >> 4) * 8;
    // B x4: matrices (n0-7,k0-7),(n0-7,k8-15),(n8-15,k0-7),(n8-15,k8-15)
    const int b_row  = warp_n * 32 + (lane & 7) + ((lane >> 4) << 3);
    const int b_koff = ((lane >> 3) & 1) * 8;

    float acc[2][4][4];
#pragma unroll
    for (int mt = 0; mt < 2; mt++)
#pragma unroll
        for (int nt = 0; nt < 4; nt++)
#pragma unroll
            for (int q = 0; q < 4; q++) acc[mt][nt][q] = 0.f;

#pragma unroll
    for (int kt = 0; kt < 8; kt++) {
        const int kb = kt * 32 + a_koff * 2;   // byte offset of k within row (A)
        uint32_t ah[2][4], al[2][4], wh[2][4], wl[2][4];
#pragma unroll
        for (int mt = 0; mt < 2; mt++) {
            uint32_t addr = sb + OFF_AH + (uint32_t)(a_row + mt * 16) * LDB + kb;
            ldsm_x4(ah[mt], addr);
            ldsm_x4(al[mt], addr + (OFF_AL - OFF_AH));
        }
        const int kbB = kt * 32 + b_koff * 2;
#pragma unroll
        for (int p = 0; p < 2; p++) {          // n-tile pairs (rows +16 per pair)
            uint32_t addr = sb + OFF_WH + (uint32_t)(b_row + p * 16) * LDB + kbB;
            ldsm_x4(wh[p], addr);
            ldsm_x4(wl[p], addr + (OFF_WL - OFF_WH));
        }
#pragma unroll
        for (int mt = 0; mt < 2; mt++) {
#pragma unroll
            for (int p = 0; p < 2; p++) {
                // nt = 2p : regs (0,1) ; nt = 2p+1 : regs (2,3)
                mma_bf16(acc[mt][2 * p],     ah[mt], wh[p][0], wh[p][1]);
                mma_bf16(acc[mt][2 * p],     ah[mt], wl[p][0], wl[p][1]);
                mma_bf16(acc[mt][2 * p],     al[mt], wh[p][0], wh[p][1]);
                mma_bf16(acc[mt][2 * p + 1], ah[mt], wh[p][2], wh[p][3]);
                mma_bf16(acc[mt][2 * p + 1], ah[mt], wl[p][2], wl[p][3]);
                mma_bf16(acc[mt][2 * p + 1], al[mt], wh[p][2], wh[p][3]);
            }
        }
    }

    // ---- epilogue ----
    const float* bi = (const float*)(smem + OFF_BI);
#pragma unroll
    for (int mt = 0; mt < 2; mt++) {
#pragma unroll
        for (int nt = 0; nt < 4; nt++) {
            int row = row0 + warp_m * 32 + mt * 16 + (lane >> 2);
            int col = warp_n * 32 + nt * 8 + (lane & 3) * 2;
            float bx = bi[col], by = bi[col + 1];
            float2 o0, o1;
            o0.x = acc[mt][nt][0] + bx; o0.y = acc[mt][nt][1] + by;
            o1.x = acc[mt][nt][2] + bx; o1.y = acc[mt][nt][3] + by;
            if (RELU) {
                o0.x = fmaxf(o0.x, 0.f); o0.y = fmaxf(o0.y, 0.f);
                o1.x = fmaxf(o1.x, 0.f); o1.y = fmaxf(o1.y, 0.f);
            }
            if (row < M)     *(float2*)&C[(size_t)row * BN + col] = o0;
            if (row + 8 < M) *(float2*)&C[(size_t)(row + 8) * BN + col] = o1;
        }
    }
}

// ---------------- MaxK: exact top-32 of 128, rewrite row in place -----------
__global__ void maxk_kernel(int M) {
    int warp = (blockIdx.x * blockDim.x + threadIdx.x) >> 5;
    int lane = threadIdx.x & 31;
    if (warp >= M) return;

    float* rowp = g_t + (size_t)warp * HIDF;
    float v[4];
    unsigned key[4];
#pragma unroll
    for (int j = 0; j < 4; j++) {
        v[j] = rowp[lane + 32 * j];
        unsigned u = __float_as_uint(v[j]);
        key[j] = (u & 0x80000000u) ? ~u : (u | 0x80000000u);
    }

    unsigned thr = 0u;
#pragma unroll
    for (int b = 31; b >= 0; b--) {
        unsigned cand = thr | (1u << b);
        int cnt = 0;
#pragma unroll
        for (int j = 0; j < 4; j++)
            cnt += __popc(__ballot_sync(0xffffffffu, key[j] >= cand));
        if (cnt >= KTOP) thr = cand;
    }

    int rem;
    {
        int cnt_gt = 0;
#pragma unroll
        for (int j = 0; j < 4; j++)
            cnt_gt += __popc(__ballot_sync(0xffffffffu, key[j] > thr));
        rem = KTOP - cnt_gt;
    }

    const float s = g_souti[warp];
    const unsigned lmlt = (1u << lane) - 1u;

#pragma unroll
    for (int j = 0; j < 4; j++) {
        unsigned beq = __ballot_sync(0xffffffffu, key[j] == thr);
        int neq  = __popc(beq);
        int take = rem < neq ? rem : neq;
        if (take < 0) take = 0;
        rem -= take;
        bool sel = (key[j] > thr) || ((key[j] == thr) && (__popc(beq & lmlt) < take));
        rowp[lane + 32 * j] = sel ? (v[j] * s) : 0.f;
    }
}

// ---------------- CSR gather ----------------------------------------------
__global__ void __launch_bounds__(256) gather_kernel(const float* __restrict__ bg, int M) {
    int w    = (blockIdx.x * blockDim.x + threadIdx.x) >> 5;
    int lane = threadIdx.x & 31;
    if (w >= M) return;

    float acc0 = 0.f, acc1 = 0.f, acc2 = 0.f, acc3 = 0.f;

    const int beg = g_rowptr[w];
    const int end = beg + g_degin[w];
    const float4* tp = (const float4*)g_t;

    int e = beg;
    for (; e + 4 <= end; e += 4) {
        int s0 = __ldg(&g_eidx[e]);
        int s1 = __ldg(&g_eidx[e + 1]);
        int s2 = __ldg(&g_eidx[e + 2]);
        int s3 = __ldg(&g_eidx[e + 3]);
        float4 v0 = __ldg(&tp[(size_t)s0 * 32 + lane]);
        float4 v1 = __ldg(&tp[(size_t)s1 * 32 + lane]);
        float4 v2 = __ldg(&tp[(size_t)s2 * 32 + lane]);
        float4 v3 = __ldg(&tp[(size_t)s3 * 32 + lane]);
        acc0 += v0.x; acc1 += v0.y; acc2 += v0.z; acc3 += v0.w;
        acc0 += v1.x; acc1 += v1.y; acc2 += v1.z; acc3 += v1.w;
        acc0 += v2.x; acc1 += v2.y; acc2 += v2.z; acc3 += v2.w;
        acc0 += v3.x; acc1 += v3.y; acc2 += v3.z; acc3 += v3.w;
    }
    for (; e < end; e++) {
        int s0 = __ldg(&g_eidx[e]);
        float4 v0 = __ldg(&tp[(size_t)s0 * 32 + lane]);
        acc0 += v0.x; acc1 += v0.y; acc2 += v0.z; acc3 += v0.w;
    }

    const float sc = g_sini[w];
    float4 b = __ldg(&((const float4*)bg)[lane]);
    float4 o;
    o.x = acc0 * sc + b.x;
    o.y = acc1 * sc + b.y;
    o.z = acc2 * sc + b.z;
    o.w = acc3 * sc + b.w;
    ((float4*)(g_h + (size_t)w * HIDF))[lane] = o;
}

// ---------------- launch -----------------------------------------------------
extern "C" void kernel_launch(void* const* d_in, const int* in_sizes, int n_in,
                              void* d_out, int out_size) {
    const float* x    = (const float*)d_in[0];
    const int*   src  = (const int*)d_in[1];
    const int*   dst  = (const int*)d_in[2];
    const float* W_in = (const float*)d_in[3];
    const float* b_in = (const float*)d_in[4];
    const float* W1   = (const float*)d_in[5];
    const float* b1   = (const float*)d_in[6];
    const float* bg1  = (const float*)d_in[7];
    const float* W2   = (const float*)d_in[8];
    const float* b2   = (const float*)d_in[9];
    const float* bg2  = (const float*)d_in[10];
    const float* Wo   = (const float*)d_in[11];
    const float* bo   = (const float*)d_in[12];
    float* out = (float*)d_out;

    const int M = in_sizes[0] / HIDF;   // 100000
    const int E = in_sizes[1];          // 1600000

    // smem: (BM + BN) hi+lo rows * 272B + bias
    const int SMEMG128 = (64 + 128) * 2 * 272 + 128 * 4;   // 104960
    const int SMEMG64  = (128 + 64) * 2 * 272 + 64 * 4;    // 104704
    cudaFuncSetAttribute(hmma_gemm_kernel<128, true>,  cudaFuncAttributeMaxDynamicSharedMemorySize, SMEMG128);
    cudaFuncSetAttribute(hmma_gemm_kernel<128, false>, cudaFuncAttributeMaxDynamicSharedMemorySize, SMEMG128);
    cudaFuncSetAttribute(hmma_gemm_kernel<64,  false>, cudaFuncAttributeMaxDynamicSharedMemorySize, SMEMG64);

    void *ph, *pt, *pdo, *pdi, *pwbh, *pwbl, *pobh, *pobl;
    cudaGetSymbolAddress(&ph,   g_h);
    cudaGetSymbolAddress(&pt,   g_t);
    cudaGetSymbolAddress(&pdo,  g_degout);
    cudaGetSymbolAddress(&pdi,  g_degin);
    cudaGetSymbolAddress(&pwbh, g_wbh);
    cudaGetSymbolAddress(&pwbl, g_wbl);
    cudaGetSymbolAddress(&pobh, g_obh);
    cudaGetSymbolAddress(&pobl, g_obl);
    float* h = (float*)ph;
    float* t = (float*)pt;
    __nv_bfloat16* wbh = (__nv_bfloat16*)pwbh;
    __nv_bfloat16* wbl = (__nv_bfloat16*)pwbl;
    __nv_bfloat16* obh = (__nv_bfloat16*)pobh;
    __nv_bfloat16* obl = (__nv_bfloat16*)pobl;

    const int TB = 256;
    const int g128_grid = (M + 63) / 64;      // BM=64 for BN=128
    const int g64_grid  = (M + 127) / 128;    // BM=128 for BN=64
    const int warp_grid = (M * 32 + TB - 1) / TB;
    const int node_grid = (M + TB - 1) / TB;
    const int edge_grid = (E + TB - 1) / TB;
    const int NB        = (M + 1023) / 1024;

    // ---- weight prep ----
    wsplit_kernel<<<64, 256>>>(W_in, wbh + 0 * 16384, wbl + 0 * 16384, 128);
    wsplit_kernel<<<64, 256>>>(W1,   wbh + 1 * 16384, wbl + 1 * 16384, 128);
    wsplit_kernel<<<64, 256>>>(W2,   wbh + 2 * 16384, wbl + 2 * 16384, 128);
    wsplit_kernel<<<32, 256>>>(Wo,   obh, obl, 64);

    // ---- degrees + CSR build ----
    cudaMemsetAsync(pdo, 0, (size_t)M * sizeof(int));
    cudaMemsetAsync(pdi, 0, (size_t)M * sizeof(int));
    hist_kernel<<<edge_grid, TB>>>(src, dst, E);
    scan_block_kernel<<<NB, 1024>>>(M);
    scan_top_kernel<<<1, 32>>>(NB);
    scan_add_kernel<<<node_grid, TB>>>(M);
    fill_kernel<<<edge_grid, TB>>>(src, dst, E);

    // ---- input projection + relu ----
    hmma_gemm_kernel<128, true><<<g128_grid, TB, SMEMG128>>>(x, wbh + 0 * 16384, wbl + 0 * 16384, b_in, h, M);

    // ---- layer 1 ----
    hmma_gemm_kernel<128, false><<<g128_grid, TB, SMEMG128>>>(h, wbh + 1 * 16384, wbl + 1 * 16384, b1, t, M);
    maxk_kernel<<<warp_grid, TB>>>(M);
    gather_kernel<<<warp_grid, TB>>>(bg1, M);

    // ---- layer 2 ----
    hmma_gemm_kernel<128, false><<<g128_grid, TB, SMEMG128>>>(h, wbh + 2 * 16384, wbl + 2 * 16384, b2, t, M);
    maxk_kernel<<<warp_grid, TB>>>(M);
    gather_kernel<<<warp_grid, TB>>>(bg2, M);

    // ---- output projection ----
    hmma_gemm_kernel<64, false><<<g64_grid, TB, SMEMG64>>>(h, obh, obl, bo, out, M);
}

// round 7
// speedup vs baseline: 1.2700x; 1.0029x over previous
#include <cuda_runtime.h>
#include <cuda_fp16.h>
#include <cstdint>

// ---------------- problem constants ----------------
#define NODES 100000
#define EDGES 1600000
#define HIDF  128
#define OUTF  64
#define KTOP  32

// ---------------- scratch (device globals; no allocation allowed) ----------
__device__ float g_h[(size_t)NODES * HIDF];      // dense activations
__device__ float g_t[(size_t)NODES * HIDF];      // GEMM output; maxk rewrites in place
__device__ int   g_degout[NODES];
__device__ int   g_degin[NODES];
__device__ float g_souti[NODES];                 // deg_out^-1/2 (clamped)
__device__ float g_sini[NODES];                  // deg_in^-1/2 (clamped)
__device__ int   g_rowptr[NODES];
__device__ int   g_cursor[NODES];
__device__ int   g_eidx[EDGES];                  // CSR-by-dst: src node ids
__device__ int   g_bsum[128];
__device__ int   g_bsumx[128];
// pre-split transposed weights, fp16, plain [n][k] row-major (k contiguous)
__device__ __half g_wbh[3 * 128 * 128];          // hi of W_in^T, W1^T, W2^T
__device__ __half g_wbl[3 * 128 * 128];          // lo
__device__ __half g_obh[64 * 128];               // W_out^T hi
__device__ __half g_obl[64 * 128];               // W_out^T lo

__device__ __forceinline__ uint32_t smem_to_u32(const void* smem_ptr) {
    uint32_t addr;
    asm("{ .reg .u64 tmp; cvta.to.shared.u64 tmp, %1; cvt.u32.u64 %0, tmp; }"
        : "=r"(addr) : "l"(smem_ptr));
    return addr;
}

__device__ __forceinline__ void ldsm_x4(uint32_t r[4], uint32_t addr) {
    asm volatile("ldmatrix.sync.aligned.m8n8.x4.shared.b16 {%0,%1,%2,%3}, [%4];"
        : "=r"(r[0]), "=r"(r[1]), "=r"(r[2]), "=r"(r[3]) : "r"(addr));
}

__device__ __forceinline__ void mma_fp16(float c[4], const uint32_t a[4],
                                         uint32_t b0, uint32_t b1) {
    asm volatile(
        "mma.sync.aligned.m16n8k16.row.col.f32.f16.f16.f32 "
        "{%0,%1,%2,%3}, {%4,%5,%6,%7}, {%8,%9}, {%0,%1,%2,%3};"
        : "+f"(c[0]), "+f"(c[1]), "+f"(c[2]), "+f"(c[3])
        : "r"(a[0]), "r"(a[1]), "r"(a[2]), "r"(a[3]), "r"(b0), "r"(b1));
}

// ---------------- degree + CSR build kernels ----------------
__global__ void hist_kernel(const int* __restrict__ src, const int* __restrict__ dst, int E) {
    int e = blockIdx.x * blockDim.x + threadIdx.x;
    if (e < E) {
        atomicAdd(&g_degout[src[e]], 1);
        atomicAdd(&g_degin[dst[e]], 1);
    }
}

__global__ void __launch_bounds__(1024) scan_block_kernel(int n) {
    __shared__ int sh[1024];
    int tid = threadIdx.x;
    int i = blockIdx.x * 1024 + tid;
    int v = (i < n) ? g_degin[i] : 0;
    sh[tid] = v;
    __syncthreads();
#pragma unroll
    for (int off = 1; off < 1024; off <<= 1) {
        int t = (tid >= off) ? sh[tid - off] : 0;
        __syncthreads();
        sh[tid] += t;
        __syncthreads();
    }
    if (i < n) g_rowptr[i] = sh[tid] - v;
    if (tid == 1023) g_bsum[blockIdx.x] = sh[1023];
}

__global__ void scan_top_kernel(int nb) {
    if (threadIdx.x == 0 && blockIdx.x == 0) {
        int acc = 0;
        for (int i = 0; i < nb; i++) { g_bsumx[i] = acc; acc += g_bsum[i]; }
    }
}

__global__ void scan_add_kernel(int n) {
    int i = blockIdx.x * blockDim.x + threadIdx.x;
    if (i < n) {
        int r = g_rowptr[i] + g_bsumx[i >> 10];
        g_rowptr[i] = r;
        g_cursor[i] = r;
        int dout = g_degout[i]; if (dout < 1) dout = 1;
        int din  = g_degin[i];  if (din  < 1) din  = 1;
        g_souti[i] = rsqrtf((float)dout);
        g_sini[i]  = rsqrtf((float)din);
    }
}

__global__ void fill_kernel(const int* __restrict__ src, const int* __restrict__ dst, int E) {
    int e = blockIdx.x * blockDim.x + threadIdx.x;
    if (e < E) {
        int d = dst[e];
        int pos = atomicAdd(&g_cursor[d], 1);
        g_eidx[pos] = src[e];
    }
}

// ---------------- weight prep: transpose + fp16 hi/lo split -----------------
// bh[n*128 + k] = hi(W[k][n]);  bl = lo.  (W is [128, N] row-major.)
__global__ void wsplit_kernel(const float* __restrict__ W,
                              __half* __restrict__ bh,
                              __half* __restrict__ bl, int N) {
    int i = blockIdx.x * blockDim.x + threadIdx.x;   // over N*128
    if (i >= N * 128) return;
    int n = i >> 7;
    int k = i & 127;
    float v = W[k * N + n];
    __half h = __float2half(v);
    __half l = __float2half(v - __half2float(h));
    bh[n * 128 + k] = h;
    bl[n * 128 + k] = l;
}

// ---------------- HMMA fp16x3 GEMM: C[M,BN] = A[M,128]@W + bias -------------
// mma.sync m16n8k16. A split hi/lo fp16 in smem (stride 136 fp16, conflict-free
// ldmatrix); W^T hi/lo staged from pre-split global. 3 products per tile:
// ah*wh + ah*wl + al*wh  (split error ~2^-22).
template <int BN, bool RELU>
__global__ void __launch_bounds__(256, 2) hmma_gemm_kernel(
    const float* __restrict__ A,
    const __half* __restrict__ wbh,
    const __half* __restrict__ wbl,
    const float* __restrict__ bias,
    float* __restrict__ C, int M)
{
    constexpr int NW = BN / 32;          // n-warps
    constexpr int MW = 8 / NW;           // m-warps
    constexpr int BM = MW * 32;          // rows per block
    constexpr int LDB = 272;             // 136 fp16 row stride, bytes
    constexpr int OFF_AH = 0;
    constexpr int OFF_AL = OFF_AH + BM * LDB;
    constexpr int OFF_WH = OFF_AL + BM * LDB;
    constexpr int OFF_WL = OFF_WH + BN * LDB;
    constexpr int OFF_BI = OFF_WL + BN * LDB;

    extern __shared__ char smem[];
    const uint32_t sb = smem_to_u32(smem);
    const int tid  = threadIdx.x;
    const int wid  = tid >> 5;
    const int lane = tid & 31;
    const int row0 = blockIdx.x * BM;
    const int warp_m = wid / NW;
    const int warp_n = wid % NW;

    // ---- stage W^T hi/lo (u32 granules: 64 per 128-fp16 row) ----
    for (int i = tid; i < BN * 64; i += 256) {
        int n = i >> 6, kp = i & 63;
        ((uint32_t*)(smem + OFF_WH + n * LDB))[kp] = ((const uint32_t*)wbh)[i];
        ((uint32_t*)(smem + OFF_WL + n * LDB))[kp] = ((const uint32_t*)wbl)[i];
    }
    if (tid < BN) ((float*)(smem + OFF_BI))[tid] = bias[tid];

    // ---- stage A tile, f32 -> (hi, lo) fp16 ----
    for (int i = tid; i < BM * 32; i += 256) {
        int r = i >> 5, c4 = i & 31;
        float4 v = make_float4(0.f, 0.f, 0.f, 0.f);
        if (row0 + r < M) v = ((const float4*)A)[(size_t)(row0 + r) * 32 + c4];
        __half h0 = __float2half(v.x);
        __half h1 = __float2half(v.y);
        __half h2 = __float2half(v.z);
        __half h3 = __float2half(v.w);
        __half l0 = __float2half(v.x - __half2float(h0));
        __half l1 = __float2half(v.y - __half2float(h1));
        __half l2 = __float2half(v.z - __half2float(h2));
        __half l3 = __float2half(v.w - __half2float(h3));
        __half2 hp0; hp0.x = h0; hp0.y = h1;
        __half2 hp1; hp1.x = h2; hp1.y = h3;
        __half2 lp0; lp0.x = l0; lp0.y = l1;
        __half2 lp1; lp1.x = l2; lp1.y = l3;
        uint32_t* dh = (uint32_t*)(smem + OFF_AH + r * LDB);
        uint32_t* dl = (uint32_t*)(smem + OFF_AL + r * LDB);
        dh[c4 * 2]     = *(uint32_t*)&hp0;
        dh[c4 * 2 + 1] = *(uint32_t*)&hp1;
        dl[c4 * 2]     = *(uint32_t*)&lp0;
        dl[c4 * 2 + 1] = *(uint32_t*)&lp1;
    }
    __syncthreads();

    // lane-derived ldmatrix offsets
    // A x4: matrices (m0-7,k0-7),(m8-15,k0-7),(m0-7,k8-15),(m8-15,k8-15)
    const int a_row  = warp_m * 32 + (lane & 15);
    const int a_koff = (lane >> 4) * 8;
    // B x4: matrices (n0-7,k0-7),(n0-7,k8-15),(n8-15,k0-7),(n8-15,k8-15)
    const int b_row  = warp_n * 32 + (lane & 7) + ((lane >> 4) << 3);
    const int b_koff = ((lane >> 3) & 1) * 8;

    float acc[2][4][4];
#pragma unroll
    for (int mt = 0; mt < 2; mt++)
#pragma unroll
        for (int nt = 0; nt < 4; nt++)
#pragma unroll
            for (int q = 0; q < 4; q++) acc[mt][nt][q] = 0.f;

#pragma unroll
    for (int kt = 0; kt < 8; kt++) {
        const int kb = kt * 32 + a_koff * 2;   // byte offset of k within row (A)
        uint32_t ah[2][4], al[2][4], wh[2][4], wl[2][4];
#pragma unroll
        for (int mt = 0; mt < 2; mt++) {
            uint32_t addr = sb + OFF_AH + (uint32_t)(a_row + mt * 16) * LDB + kb;
            ldsm_x4(ah[mt], addr);
            ldsm_x4(al[mt], addr + (OFF_AL - OFF_AH));
        }
        const int kbB = kt * 32 + b_koff * 2;
#pragma unroll
        for (int p = 0; p < 2; p++) {          // n-tile pairs (rows +16 per pair)
            uint32_t addr = sb + OFF_WH + (uint32_t)(b_row + p * 16) * LDB + kbB;
            ldsm_x4(wh[p], addr);
            ldsm_x4(wl[p], addr + (OFF_WL - OFF_WH));
        }
#pragma unroll
        for (int mt = 0; mt < 2; mt++) {
#pragma unroll
            for (int p = 0; p < 2; p++) {
                // nt = 2p : regs (0,1) ; nt = 2p+1 : regs (2,3)
                mma_fp16(acc[mt][2 * p],     ah[mt], wh[p][0], wh[p][1]);
                mma_fp16(acc[mt][2 * p],     ah[mt], wl[p][0], wl[p][1]);
                mma_fp16(acc[mt][2 * p],     al[mt], wh[p][0], wh[p][1]);
                mma_fp16(acc[mt][2 * p + 1], ah[mt], wh[p][2], wh[p][3]);
                mma_fp16(acc[mt][2 * p + 1], ah[mt], wl[p][2], wl[p][3]);
                mma_fp16(acc[mt][2 * p + 1], al[mt], wh[p][2], wh[p][3]);
            }
        }
    }

    // ---- epilogue ----
    const float* bi = (const float*)(smem + OFF_BI);
#pragma unroll
    for (int mt = 0; mt < 2; mt++) {
#pragma unroll
        for (int nt = 0; nt < 4; nt++) {
            int row = row0 + warp_m * 32 + mt * 16 + (lane >> 2);
            int col = warp_n * 32 + nt * 8 + (lane & 3) * 2;
            float bx = bi[col], by = bi[col + 1];
            float2 o0, o1;
            o0.x = acc[mt][nt][0] + bx; o0.y = acc[mt][nt][1] + by;
            o1.x = acc[mt][nt][2] + bx; o1.y = acc[mt][nt][3] + by;
            if (RELU) {
                o0.x = fmaxf(o0.x, 0.f); o0.y = fmaxf(o0.y, 0.f);
                o1.x = fmaxf(o1.x, 0.f); o1.y = fmaxf(o1.y, 0.f);
            }
            if (row < M)     *(float2*)&C[(size_t)row * BN + col] = o0;
            if (row + 8 < M) *(float2*)&C[(size_t)(row + 8) * BN + col] = o1;
        }
    }
}

// ---------------- MaxK: exact top-32 of 128, rewrite row in place -----------
__global__ void maxk_kernel(int M) {
    int warp = (blockIdx.x * blockDim.x + threadIdx.x) >> 5;
    int lane = threadIdx.x & 31;
    if (warp >= M) return;

    float* rowp = g_t + (size_t)warp * HIDF;
    float v[4];
    unsigned key[4];
#pragma unroll
    for (int j = 0; j < 4; j++) {
        v[j] = rowp[lane + 32 * j];
        unsigned u = __float_as_uint(v[j]);
        key[j] = (u & 0x80000000u) ? ~u : (u | 0x80000000u);
    }

    unsigned thr = 0u;
#pragma unroll
    for (int b = 31; b >= 0; b--) {
        unsigned cand = thr | (1u << b);
        int cnt = 0;
#pragma unroll
        for (int j = 0; j < 4; j++)
            cnt += __popc(__ballot_sync(0xffffffffu, key[j] >= cand));
        if (cnt >= KTOP) thr = cand;
    }

    int rem;
    {
        int cnt_gt = 0;
#pragma unroll
        for (int j = 0; j < 4; j++)
            cnt_gt += __popc(__ballot_sync(0xffffffffu, key[j] > thr));
        rem = KTOP - cnt_gt;
    }

    const float s = g_souti[warp];
    const unsigned lmlt = (1u << lane) - 1u;

#pragma unroll
    for (int j = 0; j < 4; j++) {
        unsigned beq = __ballot_sync(0xffffffffu, key[j] == thr);
        int neq  = __popc(beq);
        int take = rem < neq ? rem : neq;
        if (take < 0) take = 0;
        rem -= take;
        bool sel = (key[j] > thr) || ((key[j] == thr) && (__popc(beq & lmlt) < take));
        rowp[lane + 32 * j] = sel ? (v[j] * s) : 0.f;
    }
}

// ---------------- CSR gather ----------------------------------------------
__global__ void __launch_bounds__(256) gather_kernel(const float* __restrict__ bg, int M) {
    int w    = (blockIdx.x * blockDim.x + threadIdx.x) >> 5;
    int lane = threadIdx.x & 31;
    if (w >= M) return;

    float acc0 = 0.f, acc1 = 0.f, acc2 = 0.f, acc3 = 0.f;

    const int beg = g_rowptr[w];
    const int end = beg + g_degin[w];
    const float4* tp = (const float4*)g_t;

    int e = beg;
    for (; e + 4 <= end; e += 4) {
        int s0 = __ldg(&g_eidx[e]);
        int s1 = __ldg(&g_eidx[e + 1]);
        int s2 = __ldg(&g_eidx[e + 2]);
        int s3 = __ldg(&g_eidx[e + 3]);
        float4 v0 = __ldg(&tp[(size_t)s0 * 32 + lane]);
        float4 v1 = __ldg(&tp[(size_t)s1 * 32 + lane]);
        float4 v2 = __ldg(&tp[(size_t)s2 * 32 + lane]);
        float4 v3 = __ldg(&tp[(size_t)s3 * 32 + lane]);
        acc0 += v0.x; acc1 += v0.y; acc2 += v0.z; acc3 += v0.w;
        acc0 += v1.x; acc1 += v1.y; acc2 += v1.z; acc3 += v1.w;
        acc0 += v2.x; acc1 += v2.y; acc2 += v2.z; acc3 += v2.w;
        acc0 += v3.x; acc1 += v3.y; acc2 += v3.z; acc3 += v3.w;
    }
    for (; e < end; e++) {
        int s0 = __ldg(&g_eidx[e]);
        float4 v0 = __ldg(&tp[(size_t)s0 * 32 + lane]);
        acc0 += v0.x; acc1 += v0.y; acc2 += v0.z; acc3 += v0.w;
    }

    const float sc = g_sini[w];
    float4 b = __ldg(&((const float4*)bg)[lane]);
    float4 o;
    o.x = acc0 * sc + b.x;
    o.y = acc1 * sc + b.y;
    o.z = acc2 * sc + b.z;
    o.w = acc3 * sc + b.w;
    ((float4*)(g_h + (size_t)w * HIDF))[lane] = o;
}

// ---------------- launch -----------------------------------------------------
extern "C" void kernel_launch(void* const* d_in, const int* in_sizes, int n_in,
                              void* d_out, int out_size) {
    const float* x    = (const float*)d_in[0];
    const int*   src  = (const int*)d_in[1];
    const int*   dst  = (const int*)d_in[2];
    const float* W_in = (const float*)d_in[3];
    const float* b_in = (const float*)d_in[4];
    const float* W1   = (const float*)d_in[5];
    const float* b1   = (const float*)d_in[6];
    const float* bg1  = (const float*)d_in[7];
    const float* W2   = (const float*)d_in[8];
    const float* b2   = (const float*)d_in[9];
    const float* bg2  = (const float*)d_in[10];
    const float* Wo   = (const float*)d_in[11];
    const float* bo   = (const float*)d_in[12];
    float* out = (float*)d_out;

    const int M = in_sizes[0] / HIDF;   // 100000
    const int E = in_sizes[1];          // 1600000

    // smem: (BM + BN) hi+lo rows * 272B + bias
    const int SMEMG128 = (64 + 128) * 2 * 272 + 128 * 4;   // 104960
    const int SMEMG64  = (128 + 64) * 2 * 272 + 64 * 4;    // 104704
    cudaFuncSetAttribute(hmma_gemm_kernel<128, true>,  cudaFuncAttributeMaxDynamicSharedMemorySize, SMEMG128);
    cudaFuncSetAttribute(hmma_gemm_kernel<128, false>, cudaFuncAttributeMaxDynamicSharedMemorySize, SMEMG128);
    cudaFuncSetAttribute(hmma_gemm_kernel<64,  false>, cudaFuncAttributeMaxDynamicSharedMemorySize, SMEMG64);

    void *ph, *pt, *pdo, *pdi, *pwbh, *pwbl, *pobh, *pobl;
    cudaGetSymbolAddress(&ph,   g_h);
    cudaGetSymbolAddress(&pt,   g_t);
    cudaGetSymbolAddress(&pdo,  g_degout);
    cudaGetSymbolAddress(&pdi,  g_degin);
    cudaGetSymbolAddress(&pwbh, g_wbh);
    cudaGetSymbolAddress(&pwbl, g_wbl);
    cudaGetSymbolAddress(&pobh, g_obh);
    cudaGetSymbolAddress(&pobl, g_obl);
    float* h = (float*)ph;
    float* t = (float*)pt;
    __half* wbh = (__half*)pwbh;
    __half* wbl = (__half*)pwbl;
    __half* obh = (__half*)pobh;
    __half* obl = (__half*)pobl;

    const int TB = 256;
    const int g128_grid = (M + 63) / 64;      // BM=64 for BN=128
    const int g64_grid  = (M + 127) / 128;    // BM=128 for BN=64
    const int warp_grid = (M * 32 + TB - 1) / TB;
    const int node_grid = (M + TB - 1) / TB;
    const int edge_grid = (E + TB - 1) / TB;
    const int NB        = (M + 1023) / 1024;

    // ---- weight prep ----
    wsplit_kernel<<<64, 256>>>(W_in, wbh + 0 * 16384, wbl + 0 * 16384, 128);
    wsplit_kernel<<<64, 256>>>(W1,   wbh + 1 * 16384, wbl + 1 * 16384, 128);
    wsplit_kernel<<<64, 256>>>(W2,   wbh + 2 * 16384, wbl + 2 * 16384, 128);
    wsplit_kernel<<<32, 256>>>(Wo,   obh, obl, 64);

    // ---- degrees + CSR build ----
    cudaMemsetAsync(pdo, 0, (size_t)M * sizeof(int));
    cudaMemsetAsync(pdi, 0, (size_t)M * sizeof(int));
    hist_kernel<<<edge_grid, TB>>>(src, dst, E);
    scan_block_kernel<<<NB, 1024>>>(M);
    scan_top_kernel<<<1, 32>>>(NB);
    scan_add_kernel<<<node_grid, TB>>>(M);
    fill_kernel<<<edge_grid, TB>>>(src, dst, E);

    // ---- input projection + relu ----
    hmma_gemm_kernel<128, true><<<g128_grid, TB, SMEMG128>>>(x, wbh + 0 * 16384, wbl + 0 * 16384, b_in, h, M);

    // ---- layer 1 ----
    hmma_gemm_kernel<128, false><<<g128_grid, TB, SMEMG128>>>(h, wbh + 1 * 16384, wbl + 1 * 16384, b1, t, M);
    maxk_kernel<<<warp_grid, TB>>>(M);
    gather_kernel<<<warp_grid, TB>>>(bg1, M);

    // ---- layer 2 ----
    hmma_gemm_kernel<128, false><<<g128_grid, TB, SMEMG128>>>(h, wbh + 2 * 16384, wbl + 2 * 16384, b2, t, M);
    maxk_kernel<<<warp_grid, TB>>>(M);
    gather_kernel<<<warp_grid, TB>>>(bg2, M);

    // ---- output projection ----
    hmma_gemm_kernel<64, false><<<g64_grid, TB, SMEMG64>>>(h, obh, obl, bo, out, M);
}

// round 8
// speedup vs baseline: 1.3529x; 1.0653x over previous
#include <cuda_runtime.h>
#include <cuda_fp16.h>
#include <cstdint>

// ---------------- problem constants ----------------
#define NODES 100000
#define EDGES 1600000
#define HIDF  128
#define OUTF  64
#define KTOP  32

// ---------------- scratch (device globals; no allocation allowed) ----------
__device__ float g_h[(size_t)NODES * HIDF];      // dense activations
__device__ float g_t[(size_t)NODES * HIDF];      // masked GEMM output (post-maxk)
__device__ int   g_degout[NODES];
__device__ int   g_degin[NODES];
__device__ float g_souti[NODES];                 // deg_out^-1/2 (clamped)
__device__ float g_sini[NODES];                  // deg_in^-1/2 (clamped)
__device__ int   g_rowptr[NODES];
__device__ int   g_cursor[NODES];
__device__ int   g_eidx[EDGES];                  // CSR-by-dst: src node ids
__device__ int   g_bsum[128];
__device__ int   g_bsumx[128];
// pre-split transposed weights, fp16, plain [n][k] row-major (k contiguous)
__device__ __half g_wbh[3 * 128 * 128];          // hi of W_in^T, W1^T, W2^T
__device__ __half g_wbl[3 * 128 * 128];          // lo
__device__ __half g_obh[64 * 128];               // W_out^T hi
__device__ __half g_obl[64 * 128];               // W_out^T lo

__device__ __forceinline__ uint32_t smem_to_u32(const void* smem_ptr) {
    uint32_t addr;
    asm("{ .reg .u64 tmp; cvta.to.shared.u64 tmp, %1; cvt.u32.u64 %0, tmp; }"
        : "=r"(addr) : "l"(smem_ptr));
    return addr;
}

__device__ __forceinline__ void ldsm_x4(uint32_t r[4], uint32_t addr) {
    asm volatile("ldmatrix.sync.aligned.m8n8.x4.shared.b16 {%0,%1,%2,%3}, [%4];"
        : "=r"(r[0]), "=r"(r[1]), "=r"(r[2]), "=r"(r[3]) : "r"(addr));
}

__device__ __forceinline__ void mma_fp16(float c[4], const uint32_t a[4],
                                         uint32_t b0, uint32_t b1) {
    asm volatile(
        "mma.sync.aligned.m16n8k16.row.col.f32.f16.f16.f32 "
        "{%0,%1,%2,%3}, {%4,%5,%6,%7}, {%8,%9}, {%0,%1,%2,%3};"
        : "+f"(c[0]), "+f"(c[1]), "+f"(c[2]), "+f"(c[3])
        : "r"(a[0]), "r"(a[1]), "r"(a[2]), "r"(a[3]), "r"(b0), "r"(b1));
}

// ---------------- degree + CSR build kernels ----------------
__global__ void hist_kernel(const int* __restrict__ src, const int* __restrict__ dst, int E) {
    int e = blockIdx.x * blockDim.x + threadIdx.x;
    if (e < E) {
        atomicAdd(&g_degout[src[e]], 1);
        atomicAdd(&g_degin[dst[e]], 1);
    }
}

__global__ void __launch_bounds__(1024) scan_block_kernel(int n) {
    __shared__ int sh[1024];
    int tid = threadIdx.x;
    int i = blockIdx.x * 1024 + tid;
    int v = (i < n) ? g_degin[i] : 0;
    sh[tid] = v;
    __syncthreads();
#pragma unroll
    for (int off = 1; off < 1024; off <<= 1) {
        int t = (tid >= off) ? sh[tid - off] : 0;
        __syncthreads();
        sh[tid] += t;
        __syncthreads();
    }
    if (i < n) g_rowptr[i] = sh[tid] - v;
    if (tid == 1023) g_bsum[blockIdx.x] = sh[1023];
}

__global__ void scan_top_kernel(int nb) {
    if (threadIdx.x == 0 && blockIdx.x == 0) {
        int acc = 0;
        for (int i = 0; i < nb; i++) { g_bsumx[i] = acc; acc += g_bsum[i]; }
    }
}

__global__ void scan_add_kernel(int n) {
    int i = blockIdx.x * blockDim.x + threadIdx.x;
    if (i < n) {
        int r = g_rowptr[i] + g_bsumx[i >> 10];
        g_rowptr[i] = r;
        g_cursor[i] = r;
        int dout = g_degout[i]; if (dout < 1) dout = 1;
        int din  = g_degin[i];  if (din  < 1) din  = 1;
        g_souti[i] = rsqrtf((float)dout);
        g_sini[i]  = rsqrtf((float)din);
    }
}

__global__ void fill_kernel(const int* __restrict__ src, const int* __restrict__ dst, int E) {
    int e = blockIdx.x * blockDim.x + threadIdx.x;
    if (e < E) {
        int d = dst[e];
        int pos = atomicAdd(&g_cursor[d], 1);
        g_eidx[pos] = src[e];
    }
}

// ---------------- weight prep: transpose + fp16 hi/lo split (all 4 W) ------
__global__ void wsplit_all_kernel(const float* __restrict__ W_in,
                                  const float* __restrict__ W1,
                                  const float* __restrict__ W2,
                                  const float* __restrict__ Wo) {
    int i = blockIdx.x * blockDim.x + threadIdx.x;
    const float* W;
    __half *bh, *bl;
    int N, idx;
    if (i < 49152) {                 // 3 * 16384
        int layer = i >> 14; idx = i & 16383;
        W  = (layer == 0) ? W_in : ((layer == 1) ? W1 : W2);
        bh = g_wbh + (layer << 14);
        bl = g_wbl + (layer << 14);
        N  = 128;
    } else if (i < 57344) {          // + 64*128
        idx = i - 49152; W = Wo; bh = g_obh; bl = g_obl; N = 64;
    } else return;
    int n = idx >> 7;
    int k = idx & 127;
    float v = W[k * N + n];
    __half h = __float2half(v);
    __half l = __float2half(v - __half2float(h));
    bh[n * 128 + k] = h;
    bl[n * 128 + k] = l;
}

// ---------------- HMMA fp16x3 GEMM (+ optional fused MaxK) ------------------
// mma.sync m16n8k16, 3 products: ah*wh + ah*wl + al*wh (split err ~2^-22).
// MAXK (BN=128 only): stage biased rows to smem, per-row exact top-32 select,
// write masked*souti to C directly (no separate maxk kernel, no extra pass).
template <int BN, bool RELU, bool MAXK>
__global__ void __launch_bounds__(256, 2) hmma_gemm_kernel(
    const float* __restrict__ A,
    const __half* __restrict__ wbh,
    const __half* __restrict__ wbl,
    const float* __restrict__ bias,
    float* __restrict__ C, int M)
{
    static_assert(!MAXK || BN == 128, "fused maxk needs full rows per block");
    constexpr int NW = BN / 32;          // n-warps
    constexpr int MW = 8 / NW;           // m-warps
    constexpr int BM = MW * 32;          // rows per block
    constexpr int LDB = 272;             // 136 fp16 row stride, bytes
    constexpr int OFF_AH = 0;
    constexpr int OFF_AL = OFF_AH + BM * LDB;
    constexpr int OFF_WH = OFF_AL + BM * LDB;
    constexpr int OFF_WL = OFF_WH + BN * LDB;
    constexpr int OFF_BI = OFF_WL + BN * LDB;

    extern __shared__ char smem[];
    const uint32_t sb = smem_to_u32(smem);
    const int tid  = threadIdx.x;
    const int wid  = tid >> 5;
    const int lane = tid & 31;
    const int row0 = blockIdx.x * BM;
    const int warp_m = wid / NW;
    const int warp_n = wid % NW;

    // ---- stage W^T hi/lo ----
    for (int i = tid; i < BN * 64; i += 256) {
        int n = i >> 6, kp = i & 63;
        ((uint32_t*)(smem + OFF_WH + n * LDB))[kp] = ((const uint32_t*)wbh)[i];
        ((uint32_t*)(smem + OFF_WL + n * LDB))[kp] = ((const uint32_t*)wbl)[i];
    }
    if (tid < BN) ((float*)(smem + OFF_BI))[tid] = bias[tid];

    // ---- stage A tile, f32 -> (hi, lo) fp16 ----
    for (int i = tid; i < BM * 32; i += 256) {
        int r = i >> 5, c4 = i & 31;
        float4 v = make_float4(0.f, 0.f, 0.f, 0.f);
        if (row0 + r < M) v = ((const float4*)A)[(size_t)(row0 + r) * 32 + c4];
        __half h0 = __float2half(v.x);
        __half h1 = __float2half(v.y);
        __half h2 = __float2half(v.z);
        __half h3 = __float2half(v.w);
        __half l0 = __float2half(v.x - __half2float(h0));
        __half l1 = __float2half(v.y - __half2float(h1));
        __half l2 = __float2half(v.z - __half2float(h2));
        __half l3 = __float2half(v.w - __half2float(h3));
        __half2 hp0; hp0.x = h0; hp0.y = h1;
        __half2 hp1; hp1.x = h2; hp1.y = h3;
        __half2 lp0; lp0.x = l0; lp0.y = l1;
        __half2 lp1; lp1.x = l2; lp1.y = l3;
        uint32_t* dh = (uint32_t*)(smem + OFF_AH + r * LDB);
        uint32_t* dl = (uint32_t*)(smem + OFF_AL + r * LDB);
        dh[c4 * 2]     = *(uint32_t*)&hp0;
        dh[c4 * 2 + 1] = *(uint32_t*)&hp1;
        dl[c4 * 2]     = *(uint32_t*)&lp0;
        dl[c4 * 2 + 1] = *(uint32_t*)&lp1;
    }
    __syncthreads();

    const int a_row  = warp_m * 32 + (lane & 15);
    const int a_koff = (lane >> 4) * 8;
    const int b_row  = warp_n * 32 + (lane & 7) + ((lane >> 4) << 3);
    const int b_koff = ((lane >> 3) & 1) * 8;

    float acc[2][4][4];
#pragma unroll
    for (int mt = 0; mt < 2; mt++)
#pragma unroll
        for (int nt = 0; nt < 4; nt++)
#pragma unroll
            for (int q = 0; q < 4; q++) acc[mt][nt][q] = 0.f;

#pragma unroll
    for (int kt = 0; kt < 8; kt++) {
        const int kb = kt * 32 + a_koff * 2;
        uint32_t ah[2][4], al[2][4], wh[2][4], wl[2][4];
#pragma unroll
        for (int mt = 0; mt < 2; mt++) {
            uint32_t addr = sb + OFF_AH + (uint32_t)(a_row + mt * 16) * LDB + kb;
            ldsm_x4(ah[mt], addr);
            ldsm_x4(al[mt], addr + (OFF_AL - OFF_AH));
        }
        const int kbB = kt * 32 + b_koff * 2;
#pragma unroll
        for (int p = 0; p < 2; p++) {
            uint32_t addr = sb + OFF_WH + (uint32_t)(b_row + p * 16) * LDB + kbB;
            ldsm_x4(wh[p], addr);
            ldsm_x4(wl[p], addr + (OFF_WL - OFF_WH));
        }
#pragma unroll
        for (int mt = 0; mt < 2; mt++) {
#pragma unroll
            for (int p = 0; p < 2; p++) {
                mma_fp16(acc[mt][2 * p],     ah[mt], wh[p][0], wh[p][1]);
                mma_fp16(acc[mt][2 * p],     ah[mt], wl[p][0], wl[p][1]);
                mma_fp16(acc[mt][2 * p],     al[mt], wh[p][0], wh[p][1]);
                mma_fp16(acc[mt][2 * p + 1], ah[mt], wh[p][2], wh[p][3]);
                mma_fp16(acc[mt][2 * p + 1], ah[mt], wl[p][2], wl[p][3]);
                mma_fp16(acc[mt][2 * p + 1], al[mt], wh[p][2], wh[p][3]);
            }
        }
    }

    const float* bi = (const float*)(smem + OFF_BI);

    if (MAXK) {
        // ---- fused epilogue: rows -> smem, exact top-32, masked write ----
        __syncthreads();                     // done reading A/W smem
        float* rbuf = (float*)smem;          // [BM][132] floats (reuses A region)
#pragma unroll
        for (int mt = 0; mt < 2; mt++) {
#pragma unroll
            for (int nt = 0; nt < 4; nt++) {
                int r   = warp_m * 32 + mt * 16 + (lane >> 2);
                int col = warp_n * 32 + nt * 8 + (lane & 3) * 2;
                float bx = bi[col], by = bi[col + 1];
                rbuf[r * 132 + col]           = acc[mt][nt][0] + bx;
                rbuf[r * 132 + col + 1]       = acc[mt][nt][1] + by;
                rbuf[(r + 8) * 132 + col]     = acc[mt][nt][2] + bx;
                rbuf[(r + 8) * 132 + col + 1] = acc[mt][nt][3] + by;
            }
        }
        __syncthreads();

        const unsigned lmlt = (1u << lane) - 1u;
#pragma unroll 1
        for (int rr = 0; rr < 8; rr++) {
            int r    = wid * 8 + rr;
            int grow = row0 + r;
            if (grow >= M) break;            // uniform per warp

            float v[4];
            unsigned key[4];
#pragma unroll
            for (int j = 0; j < 4; j++) {
                v[j] = rbuf[r * 132 + lane + 32 * j];
                unsigned u = __float_as_uint(v[j]);
                key[j] = (u & 0x80000000u) ? ~u : (u | 0x80000000u);
            }
            unsigned thr = 0u;
#pragma unroll
            for (int b = 31; b >= 0; b--) {
                unsigned cand = thr | (1u << b);
                int cnt = 0;
#pragma unroll
                for (int j = 0; j < 4; j++)
                    cnt += __popc(__ballot_sync(0xffffffffu, key[j] >= cand));
                if (cnt >= KTOP) thr = cand;
            }
            int rem;
            {
                int cnt_gt = 0;
#pragma unroll
                for (int j = 0; j < 4; j++)
                    cnt_gt += __popc(__ballot_sync(0xffffffffu, key[j] > thr));
                rem = KTOP - cnt_gt;
            }
            const float s = g_souti[grow];
            float* rowp = C + (size_t)grow * HIDF;
#pragma unroll
            for (int j = 0; j < 4; j++) {
                unsigned beq = __ballot_sync(0xffffffffu, key[j] == thr);
                int neq  = __popc(beq);
                int take = rem < neq ? rem : neq;
                if (take < 0) take = 0;
                rem -= take;
                bool sel = (key[j] > thr) ||
                           ((key[j] == thr) && (__popc(beq & lmlt) < take));
                rowp[lane + 32 * j] = sel ? (v[j] * s) : 0.f;
            }
        }
    } else {
        // ---- regular epilogue ----
#pragma unroll
        for (int mt = 0; mt < 2; mt++) {
#pragma unroll
            for (int nt = 0; nt < 4; nt++) {
                int row = row0 + warp_m * 32 + mt * 16 + (lane >> 2);
                int col = warp_n * 32 + nt * 8 + (lane & 3) * 2;
                float bx = bi[col], by = bi[col + 1];
                float2 o0, o1;
                o0.x = acc[mt][nt][0] + bx; o0.y = acc[mt][nt][1] + by;
                o1.x = acc[mt][nt][2] + bx; o1.y = acc[mt][nt][3] + by;
                if (RELU) {
                    o0.x = fmaxf(o0.x, 0.f); o0.y = fmaxf(o0.y, 0.f);
                    o1.x = fmaxf(o1.x, 0.f); o1.y = fmaxf(o1.y, 0.f);
                }
                if (row < M)     *(float2*)&C[(size_t)row * BN + col] = o0;
                if (row + 8 < M) *(float2*)&C[(size_t)(row + 8) * BN + col] = o1;
            }
        }
    }
}

// ---------------- CSR gather ----------------------------------------------
__global__ void __launch_bounds__(256) gather_kernel(const float* __restrict__ bg, int M) {
    int w    = (blockIdx.x * blockDim.x + threadIdx.x) >> 5;
    int lane = threadIdx.x & 31;
    if (w >= M) return;

    float acc0 = 0.f, acc1 = 0.f, acc2 = 0.f, acc3 = 0.f;

    const int beg = g_rowptr[w];
    const int end = beg + g_degin[w];
    const float4* tp = (const float4*)g_t;

    int e = beg;
    for (; e + 4 <= end; e += 4) {
        int s0 = __ldg(&g_eidx[e]);
        int s1 = __ldg(&g_eidx[e + 1]);
        int s2 = __ldg(&g_eidx[e + 2]);
        int s3 = __ldg(&g_eidx[e + 3]);
        float4 v0 = __ldg(&tp[(size_t)s0 * 32 + lane]);
        float4 v1 = __ldg(&tp[(size_t)s1 * 32 + lane]);
        float4 v2 = __ldg(&tp[(size_t)s2 * 32 + lane]);
        float4 v3 = __ldg(&tp[(size_t)s3 * 32 + lane]);
        acc0 += v0.x; acc1 += v0.y; acc2 += v0.z; acc3 += v0.w;
        acc0 += v1.x; acc1 += v1.y; acc2 += v1.z; acc3 += v1.w;
        acc0 += v2.x; acc1 += v2.y; acc2 += v2.z; acc3 += v2.w;
        acc0 += v3.x; acc1 += v3.y; acc2 += v3.z; acc3 += v3.w;
    }
    for (; e < end; e++) {
        int s0 = __ldg(&g_eidx[e]);
        float4 v0 = __ldg(&tp[(size_t)s0 * 32 + lane]);
        acc0 += v0.x; acc1 += v0.y; acc2 += v0.z; acc3 += v0.w;
    }

    const float sc = g_sini[w];
    float4 b = __ldg(&((const float4*)bg)[lane]);
    float4 o;
    o.x = acc0 * sc + b.x;
    o.y = acc1 * sc + b.y;
    o.z = acc2 * sc + b.z;
    o.w = acc3 * sc + b.w;
    ((float4*)(g_h + (size_t)w * HIDF))[lane] = o;
}

// ---------------- launch -----------------------------------------------------
extern "C" void kernel_launch(void* const* d_in, const int* in_sizes, int n_in,
                              void* d_out, int out_size) {
    const float* x    = (const float*)d_in[0];
    const int*   src  = (const int*)d_in[1];
    const int*   dst  = (const int*)d_in[2];
    const float* W_in = (const float*)d_in[3];
    const float* b_in = (const float*)d_in[4];
    const float* W1   = (const float*)d_in[5];
    const float* b1   = (const float*)d_in[6];
    const float* bg1  = (const float*)d_in[7];
    const float* W2   = (const float*)d_in[8];
    const float* b2   = (const float*)d_in[9];
    const float* bg2  = (const float*)d_in[10];
    const float* Wo   = (const float*)d_in[11];
    const float* bo   = (const float*)d_in[12];
    float* out = (float*)d_out;

    const int M = in_sizes[0] / HIDF;   // 100000
    const int E = in_sizes[1];          // 1600000

    // side stream + events: created once on the (un-captured) correctness
    // call; only record/wait — both capture-legal — happen afterwards.
    static bool s_init = false;
    static cudaStream_t s1;
    static cudaEvent_t e_root, e_scan, e_fill;
    if (!s_init) {
        cudaStreamCreateWithFlags(&s1, cudaStreamNonBlocking);
        cudaEventCreateWithFlags(&e_root, cudaEventDisableTiming);
        cudaEventCreateWithFlags(&e_scan, cudaEventDisableTiming);
        cudaEventCreateWithFlags(&e_fill, cudaEventDisableTiming);
        s_init = true;
    }

    const int SMEMG128 = (64 + 128) * 2 * 272 + 128 * 4;   // 104960
    const int SMEMG64  = (128 + 64) * 2 * 272 + 64 * 4;    // 104704
    cudaFuncSetAttribute((const void*)hmma_gemm_kernel<128, true,  false>, cudaFuncAttributeMaxDynamicSharedMemorySize, SMEMG128);
    cudaFuncSetAttribute((const void*)hmma_gemm_kernel<128, false, true>,  cudaFuncAttributeMaxDynamicSharedMemorySize, SMEMG128);
    cudaFuncSetAttribute((const void*)hmma_gemm_kernel<64,  false, false>, cudaFuncAttributeMaxDynamicSharedMemorySize, SMEMG64);

    void *ph, *pt, *pdo, *pdi, *pwbh, *pwbl, *pobh, *pobl;
    cudaGetSymbolAddress(&ph,   g_h);
    cudaGetSymbolAddress(&pt,   g_t);
    cudaGetSymbolAddress(&pdo,  g_degout);
    cudaGetSymbolAddress(&pdi,  g_degin);
    cudaGetSymbolAddress(&pwbh, g_wbh);
    cudaGetSymbolAddress(&pwbl, g_wbl);
    cudaGetSymbolAddress(&pobh, g_obh);
    cudaGetSymbolAddress(&pobl, g_obl);
    float* h = (float*)ph;
    float* t = (float*)pt;
    __half* wbh = (__half*)pwbh;
    __half* wbl = (__half*)pwbl;
    __half* obh = (__half*)pobh;
    __half* obl = (__half*)pobl;

    const int TB = 256;
    const int g128_grid = (M + 63) / 64;      // BM=64 for BN=128
    const int g64_grid  = (M + 127) / 128;    // BM=128 for BN=64
    const int warp_grid = (M * 32 + TB - 1) / TB;
    const int node_grid = (M + TB - 1) / TB;
    const int edge_grid = (E + TB - 1) / TB;
    const int NB        = (M + 1023) / 1024;

    // fork: CSR build on side stream, overlapped with wsplit + first 2 GEMMs
    cudaEventRecord(e_root, 0);
    cudaStreamWaitEvent(s1, e_root, 0);

    cudaMemsetAsync(pdo, 0, (size_t)M * sizeof(int), s1);
    cudaMemsetAsync(pdi, 0, (size_t)M * sizeof(int), s1);
    hist_kernel<<<edge_grid, TB, 0, s1>>>(src, dst, E);
    scan_block_kernel<<<NB, 1024, 0, s1>>>(M);
    scan_top_kernel<<<1, 32, 0, s1>>>(NB);
    scan_add_kernel<<<node_grid, TB, 0, s1>>>(M);
    cudaEventRecord(e_scan, s1);               // souti/sini/rowptr ready
    fill_kernel<<<edge_grid, TB, 0, s1>>>(src, dst, E);
    cudaEventRecord(e_fill, s1);               // eidx ready

    // main stream: weights + input projection
    wsplit_all_kernel<<<224, 256>>>(W_in, W1, W2, Wo);
    hmma_gemm_kernel<128, true, false><<<g128_grid, TB, SMEMG128>>>(
        x, wbh + 0 * 16384, wbl + 0 * 16384, b_in, h, M);

    // layer 1 (gemm+maxk fused; needs souti)
    cudaStreamWaitEvent((cudaStream_t)0, e_scan, 0);
    hmma_gemm_kernel<128, false, true><<<g128_grid, TB, SMEMG128>>>(
        h, wbh + 1 * 16384, wbl + 1 * 16384, b1, t, M);
    cudaStreamWaitEvent((cudaStream_t)0, e_fill, 0);
    gather_kernel<<<warp_grid, TB>>>(bg1, M);

    // layer 2
    hmma_gemm_kernel<128, false, true><<<g128_grid, TB, SMEMG128>>>(
        h, wbh + 2 * 16384, wbl + 2 * 16384, b2, t, M);
    gather_kernel<<<warp_grid, TB>>>(bg2, M);

    // output projection
    hmma_gemm_kernel<64, false, false><<<g64_grid, TB, SMEMG64>>>(
        h, obh, obl, bo, out, M);
}